// round 10
// baseline (speedup 1.0000x reference)
#include <cuda_runtime.h>

// Per-frame table: M[f] = initial_extrinsics[f] @ inv(c2w[f]). Row 3 is
// exactly (0,0,0,1) so only rows 0..2 are stored/read. 64B stride keeps
// entries line-aligned.
#define NF_MAX 10000
__device__ __align__(128) float4 g_M[NF_MAX * 4];

// Cross-block sync state (reset by the last block each launch -> replay-safe).
__device__ int g_done_pre;
__device__ int g_done_blocks;

#define GATHER_ILP 4

__device__ __forceinline__ void precompute_frame(
        const float* __restrict__ r, const float* __restrict__ t,
        const float* __restrict__ E, int f) {
    float v0 = r[3 * f + 0];
    float v1 = r[3 * f + 1];
    float v2 = r[3 * f + 2];

    float n = sqrtf(v0 * v0 + v1 * v1 + v2 * v2) + 1e-15f;
    float sn, cn;
    __sincosf(n, &sn, &cn);
    float a = sn / n;
    float b = (1.0f - cn) / (n * n);

    // Reference vec2skew (transpose of standard skew)
    float S[3][3] = {{0.0f,  v2, -v1},
                     {-v2, 0.0f,  v0},
                     { v1, -v0, 0.0f}};
    float S2[3][3];
#pragma unroll
    for (int i = 0; i < 3; i++)
#pragma unroll
        for (int j = 0; j < 3; j++)
            S2[i][j] = S[i][0] * S[0][j] + S[i][1] * S[1][j] + S[i][2] * S[2][j];

    float R[3][3];
#pragma unroll
    for (int i = 0; i < 3; i++)
#pragma unroll
        for (int j = 0; j < 3; j++)
            R[i][j] = (i == j ? 1.0f : 0.0f) + a * S[i][j] + b * S2[i][j];

    float tv0 = t[3 * f + 0];
    float tv1 = t[3 * f + 1];
    float tv2 = t[3 * f + 2];

    float Inv[3][4];
#pragma unroll
    for (int i = 0; i < 3; i++) {
        Inv[i][0] = R[0][i];
        Inv[i][1] = R[1][i];
        Inv[i][2] = R[2][i];
        Inv[i][3] = -(R[0][i] * tv0 + R[1][i] * tv1 + R[2][i] * tv2);
    }

    const float4* E0 = (const float4*)(E + 16 * f);
#pragma unroll
    for (int i = 0; i < 3; i++) {
        float4 e = E0[i];
        float4 row;
        row.x = e.x * Inv[0][0] + e.y * Inv[1][0] + e.z * Inv[2][0];
        row.y = e.x * Inv[0][1] + e.y * Inv[1][1] + e.z * Inv[2][1];
        row.z = e.x * Inv[0][2] + e.y * Inv[1][2] + e.z * Inv[2][2];
        row.w = e.x * Inv[0][3] + e.y * Inv[1][3] + e.z * Inv[2][3] + e.w;
        g_M[f * 4 + i] = row;
    }
}

// ---------------------------------------------------------------------------
// Fused kernel: blocks [0, P) build the table first (hardware schedules low
// bids in wave 1, so they are always resident -> no deadlock), every block
// spin-waits on g_done_pre, then gathers. Last block resets the counters.
// ---------------------------------------------------------------------------
__global__ void __launch_bounds__(256, 8) fused_kernel(
        const float* __restrict__ r,
        const float* __restrict__ t,
        const float* __restrict__ E,
        const int* __restrict__ cam,
        float4* __restrict__ out,
        int n_chunks, int nf, int P) {
    // ---- phase A: precompute (first P blocks) ----
    if ((int)blockIdx.x < P) {
        int f = blockIdx.x * blockDim.x + threadIdx.x;
        if (f < nf) precompute_frame(r, t, E, f);
        __threadfence();
        __syncthreads();
        if (threadIdx.x == 0) atomicAdd(&g_done_pre, 1);
    }

    // ---- barrier: wait for full table ----
    if (threadIdx.x == 0) {
        while (atomicAdd(&g_done_pre, 0) < P) __nanosleep(64);
    }
    __syncthreads();
    __threadfence();   // order table reads after the flag

    // ---- phase B: gather ----
    int base = blockIdx.x * (blockDim.x * GATHER_ILP) + threadIdx.x;
    const float4 bottom = make_float4(0.0f, 0.0f, 0.0f, 1.0f);

    if (base + (GATHER_ILP - 1) * blockDim.x < n_chunks) {
        float4 v[GATHER_ILP];
#pragma unroll
        for (int k = 0; k < GATHER_ILP; k++) {
            int c = base + k * blockDim.x;
            int ray = c >> 2;
            int q   = c & 3;
            if (q == 3) {
                v[k] = bottom;
            } else {
                int f = __ldg(&cam[ray]);
                f = min(max(f, 0), nf - 1);
                v[k] = __ldg(&g_M[f * 4 + q]);
            }
        }
#pragma unroll
        for (int k = 0; k < GATHER_ILP; k++)
            out[base + k * blockDim.x] = v[k];
    } else {
#pragma unroll
        for (int k = 0; k < GATHER_ILP; k++) {
            int c = base + k * blockDim.x;
            if (c < n_chunks) {
                int ray = c >> 2;
                int q   = c & 3;
                if (q == 3) {
                    out[c] = bottom;
                } else {
                    int f = __ldg(&cam[ray]);
                    f = min(max(f, 0), nf - 1);
                    out[c] = __ldg(&g_M[f * 4 + q]);
                }
            }
        }
    }

    // ---- cleanup: last block resets counters for the next graph replay ----
    __syncthreads();
    if (threadIdx.x == 0) {
        int done = atomicAdd(&g_done_blocks, 1);
        if (done == (int)gridDim.x - 1) {
            g_done_pre = 0;
            g_done_blocks = 0;
            __threadfence();
        }
    }
}

extern "C" void kernel_launch(void* const* d_in, const int* in_sizes, int n_in,
                              void* d_out, int out_size) {
    const float* r   = (const float*)d_in[0];   // (NF, 3)
    const float* t   = (const float*)d_in[1];   // (NF, 3)
    const float* E   = (const float*)d_in[2];   // (NF, 4, 4)
    const int*   cam = (const int*)d_in[3];     // (NR,) int32

    int nf = in_sizes[0] / 3;
    if (nf > NF_MAX) nf = NF_MAX;
    int nr = in_sizes[3];

    int threads = 256;
    int n_chunks = nr * 4;
    int per_block = threads * GATHER_ILP;
    int grid = (n_chunks + per_block - 1) / per_block;
    int P = (nf + threads - 1) / threads;       // precompute blocks (<= grid)
    if (P > grid) P = grid;

    fused_kernel<<<grid, threads>>>(r, t, E, cam, (float4*)d_out,
                                    n_chunks, nf, P);
}

// round 12
// speedup vs baseline: 1.2866x; 1.2866x over previous
#include <cuda_runtime.h>

// Per-frame table: M[f] = initial_extrinsics[f] @ inv(c2w[f]). Row 3 is
// exactly (0,0,0,1) so only rows 0..2 are stored/read. 64B stride keeps
// each entry line-aligned.
#define NF_MAX 10000
__device__ __align__(128) float4 g_M[NF_MAX * 4];

#define GATHER_ILP 4

// PDL primitives via inline PTX (intrinsics not exposed by this toolchain).
__device__ __forceinline__ void pdl_launch_dependents() {
    asm volatile("griddepcontrol.launch_dependents;");
}
__device__ __forceinline__ void pdl_wait() {
    asm volatile("griddepcontrol.wait;" ::: "memory");
}

// ---------------------------------------------------------------------------
// Phase 1: per-frame precompute, fp32, 64-thread blocks. Signals dependent
// launch (PDL) once its table stores are issued.
// ---------------------------------------------------------------------------
__global__ void precompute_kernel(const float* __restrict__ r,
                                  const float* __restrict__ t,
                                  const float* __restrict__ E,
                                  int nf) {
    int f = blockIdx.x * blockDim.x + threadIdx.x;
    if (f < nf) {
        float v0 = r[3 * f + 0];
        float v1 = r[3 * f + 1];
        float v2 = r[3 * f + 2];

        float n = sqrtf(v0 * v0 + v1 * v1 + v2 * v2) + 1e-15f;
        float sn, cn;
        __sincosf(n, &sn, &cn);
        float a = sn / n;
        float b = (1.0f - cn) / (n * n);

        // Reference vec2skew (transpose of standard skew)
        float S[3][3] = {{0.0f,  v2, -v1},
                         {-v2, 0.0f,  v0},
                         { v1, -v0, 0.0f}};
        float S2[3][3];
#pragma unroll
        for (int i = 0; i < 3; i++)
#pragma unroll
            for (int j = 0; j < 3; j++)
                S2[i][j] = S[i][0] * S[0][j] + S[i][1] * S[1][j] + S[i][2] * S[2][j];

        float R[3][3];
#pragma unroll
        for (int i = 0; i < 3; i++)
#pragma unroll
            for (int j = 0; j < 3; j++)
                R[i][j] = (i == j ? 1.0f : 0.0f) + a * S[i][j] + b * S2[i][j];

        float tv0 = t[3 * f + 0];
        float tv1 = t[3 * f + 1];
        float tv2 = t[3 * f + 2];

        float Inv[3][4];
#pragma unroll
        for (int i = 0; i < 3; i++) {
            Inv[i][0] = R[0][i];
            Inv[i][1] = R[1][i];
            Inv[i][2] = R[2][i];
            Inv[i][3] = -(R[0][i] * tv0 + R[1][i] * tv1 + R[2][i] * tv2);
        }

        const float4* E0 = (const float4*)(E + 16 * f);
#pragma unroll
        for (int i = 0; i < 3; i++) {
            float4 e = E0[i];
            float4 row;
            row.x = e.x * Inv[0][0] + e.y * Inv[1][0] + e.z * Inv[2][0];
            row.y = e.x * Inv[0][1] + e.y * Inv[1][1] + e.z * Inv[2][1];
            row.z = e.x * Inv[0][2] + e.y * Inv[1][2] + e.z * Inv[2][2];
            row.w = e.x * Inv[0][3] + e.y * Inv[1][3] + e.z * Inv[2][3] + e.w;
            g_M[f * 4 + i] = row;
        }
    }
    // Allow dependent grid to begin launching; it still gates table reads on
    // griddepcontrol.wait (completes only after this grid fully retires).
    pdl_launch_dependents();
}

// ---------------------------------------------------------------------------
// Phase 2: gather (PDL dependent). Front-loads all table-independent work
// (cam loads + index math) BEFORE griddepcontrol.wait, overlapping it with
// the precompute tail. q==3 lane stores the constant bottom row, no load.
// ---------------------------------------------------------------------------
__global__ void __launch_bounds__(256) gather_kernel(
        const int* __restrict__ cam,
        float4* __restrict__ out,
        int n_chunks, int nf) {
    int base = blockIdx.x * (blockDim.x * GATHER_ILP) + threadIdx.x;
    const float4 bottom = make_float4(0.0f, 0.0f, 0.0f, 1.0f);

    if (base + (GATHER_ILP - 1) * blockDim.x < n_chunks) {
        // --- table-independent prologue: cam gathers + clamped indices ---
        int fq[GATHER_ILP];
#pragma unroll
        for (int k = 0; k < GATHER_ILP; k++) {
            int c = base + k * blockDim.x;
            int ray = c >> 2;
            int q   = c & 3;
            int f = (q == 3) ? 0 : __ldg(&cam[ray]);
            f = min(max(f, 0), nf - 1);
            fq[k] = f * 4 + q;
        }

        pdl_wait();   // table fully written + visible after this

        float4 v[GATHER_ILP];
#pragma unroll
        for (int k = 0; k < GATHER_ILP; k++) {
            int c = base + k * blockDim.x;
            v[k] = ((c & 3) == 3) ? bottom : __ldg(&g_M[fq[k]]);
        }
#pragma unroll
        for (int k = 0; k < GATHER_ILP; k++)
            out[base + k * blockDim.x] = v[k];
    } else {
        pdl_wait();
#pragma unroll
        for (int k = 0; k < GATHER_ILP; k++) {
            int c = base + k * blockDim.x;
            if (c < n_chunks) {
                int ray = c >> 2;
                int q   = c & 3;
                if (q == 3) {
                    out[c] = bottom;
                } else {
                    int f = __ldg(&cam[ray]);
                    f = min(max(f, 0), nf - 1);
                    out[c] = __ldg(&g_M[f * 4 + q]);
                }
            }
        }
    }
}

extern "C" void kernel_launch(void* const* d_in, const int* in_sizes, int n_in,
                              void* d_out, int out_size) {
    const float* r   = (const float*)d_in[0];   // (NF, 3)
    const float* t   = (const float*)d_in[1];   // (NF, 3)
    const float* E   = (const float*)d_in[2];   // (NF, 4, 4)
    const int*   cam = (const int*)d_in[3];     // (NR,) int32

    int nf = in_sizes[0] / 3;
    if (nf > NF_MAX) nf = NF_MAX;
    int nr = in_sizes[3];

    precompute_kernel<<<(nf + 63) / 64, 64>>>(r, t, E, nf);

    int n_chunks = nr * 4;
    int threads = 256;
    int per_block = threads * GATHER_ILP;
    int grid = (n_chunks + per_block - 1) / per_block;

    // Launch gather as a programmatic dependent of precompute: its blocks may
    // begin (and run their cam-load prologue) while precompute drains; the
    // griddepcontrol.wait inside gates the table reads.
    cudaLaunchConfig_t cfg = {};
    cfg.gridDim = dim3((unsigned)grid);
    cfg.blockDim = dim3((unsigned)threads);
    cfg.dynamicSmemBytes = 0;
    cfg.stream = 0;  // same (capture) stream as the <<<>>> launch above
    cudaLaunchAttribute attrs[1];
    attrs[0].id = cudaLaunchAttributeProgrammaticStreamSerialization;
    attrs[0].val.programmaticStreamSerializationAllowed = 1;
    cfg.attrs = attrs;
    cfg.numAttrs = 1;
    cudaLaunchKernelEx(&cfg, gather_kernel, cam, (float4*)d_out, n_chunks, nf);
}